// round 2
// baseline (speedup 1.0000x reference)
#include <cuda_runtime.h>

#define Bb 16
#define Ff 128
#define Nn 2048
#define BN (Bb*Nn)          // 32768
#define TOT (Bb*Ff*Nn)      // 4194304

// scratch (allocation-free: __device__ globals)
__device__ float  g_s[BN];
__device__ double g_sum;
__device__ double g_sumsq;
__device__ float  g_scale;   // 1/std
__device__ float  g_bias;

__global__ void k_zero() {
    g_sum = 0.0;
    g_sumsq = 0.0;
}

// One thread per (b, n): s[b,n] = sum_f v[f]*emb[b,f,n]; also accumulate
// global sum and sum-of-squares for the std.
__global__ void k_fused(const float* __restrict__ emb, const float* __restrict__ v) {
    __shared__ float sv[Ff];
    __shared__ float red_sum[8];
    __shared__ float red_sq[8];

    int tid = threadIdx.x;
    if (tid < Ff) sv[tid] = v[tid];
    __syncthreads();

    int idx = blockIdx.x * blockDim.x + tid;   // 0..BN-1
    int b = idx >> 11;
    int n = idx & (Nn - 1);
    const float* p = emb + (size_t)b * Ff * Nn + n;

    float s = 0.f, sum = 0.f, sq = 0.f;
#pragma unroll
    for (int f = 0; f < Ff; f++) {
        float x = __ldg(p + (size_t)f * Nn);
        s   = fmaf(sv[f], x, s);
        sum += x;
        sq  = fmaf(x, x, sq);
    }
    g_s[idx] = s;

    // block reduce sum & sq
    int lane = tid & 31;
    int wid  = tid >> 5;
#pragma unroll
    for (int o = 16; o > 0; o >>= 1) {
        sum += __shfl_xor_sync(0xffffffffu, sum, o);
        sq  += __shfl_xor_sync(0xffffffffu, sq, o);
    }
    if (lane == 0) { red_sum[wid] = sum; red_sq[wid] = sq; }
    __syncthreads();
    if (wid == 0) {
        float rs = (lane < 8) ? red_sum[lane] : 0.f;
        float rq = (lane < 8) ? red_sq[lane]  : 0.f;
#pragma unroll
        for (int o = 4; o > 0; o >>= 1) {
            rs += __shfl_xor_sync(0xffffffffu, rs, o);
            rq += __shfl_xor_sync(0xffffffffu, rq, o);
        }
        if (lane == 0) {
            atomicAdd(&g_sum, (double)rs);
            atomicAdd(&g_sumsq, (double)rq);
        }
    }
}

__global__ void k_finalize(const float* __restrict__ bias) {
    double m  = (double)TOT;
    double var = (g_sumsq - g_sum * g_sum / m) / (m - 1.0);
    g_scale = (float)(1.0 / sqrt(var));
    g_bias  = bias[0];
}

// One block per output row (b,i); each thread writes one float4 of j.
__global__ void __launch_bounds__(512, 4) k_main(float* __restrict__ out) {
    int row = blockIdx.x;             // 0..BN-1
    int b   = row >> 11;              // row / N
    float scale = g_scale;
    float a = fmaf(g_s[row], scale, g_bias);   // s_i*scale + bias

    const float4* srow = (const float4*)(g_s + (size_t)b * Nn);
    float4 sj = __ldg(srow + threadIdx.x);

    float4 r;
    {
        float t = fmaf(sj.x, scale, a);
        r.x = __fdividef(1.f, 1.f + __expf(-t));
        t = fmaf(sj.y, scale, a);
        r.y = __fdividef(1.f, 1.f + __expf(-t));
        t = fmaf(sj.z, scale, a);
        r.z = __fdividef(1.f, 1.f + __expf(-t));
        t = fmaf(sj.w, scale, a);
        r.w = __fdividef(1.f, 1.f + __expf(-t));
    }

    float4* orow = (float4*)(out + (size_t)row * Nn);
    orow[threadIdx.x] = r;
}

extern "C" void kernel_launch(void* const* d_in, const int* in_sizes, int n_in,
                              void* d_out, int out_size) {
    // inputs: adj_in [B,N,N] (unused), emb_in [B,F,N], v [F], b [1]
    const float* emb  = (const float*)d_in[1];
    const float* v    = (const float*)d_in[2];
    const float* bias = (const float*)d_in[3];
    float* out = (float*)d_out;

    k_zero<<<1, 1>>>();
    k_fused<<<BN / 256, 256>>>(emb, v);
    k_finalize<<<1, 1>>>(bias);
    k_main<<<BN, 512>>>(out);
}

// round 3
// speedup vs baseline: 1.2193x; 1.2193x over previous
#include <cuda_runtime.h>
#include <math.h>

#define Bb 16
#define Ff 128
#define Nn 2048
#define BN (Bb*Nn)          // 32768
#define TOT (Bb*Ff*Nn)      // 4194304

// scratch (allocation-free: __device__ globals)
__device__ float  g_s[BN];
__device__ float  g_E[BN];
__device__ double g_sum   = 0.0;
__device__ double g_sumsq = 0.0;

// ---------------------------------------------------------------------------
// Pass 1: s[b,n] = sum_f v[f]*emb[b,f,n]; accumulate global sum / sum-of-squares.
// Block = 256 threads = 64 n-positions x 4 f-chunks (32 f each). Grid = 512.
// ---------------------------------------------------------------------------
__global__ void __launch_bounds__(256) k_fused(const float* __restrict__ emb,
                                               const float* __restrict__ v) {
    __shared__ float sv[Ff];
    __shared__ float spart[256];
    __shared__ float red_sum[8];
    __shared__ float red_sq[8];

    int tid = threadIdx.x;
    if (tid < Ff) sv[tid] = v[tid];
    __syncthreads();

    int b  = blockIdx.x >> 5;          // 0..15
    int ng = blockIdx.x & 31;          // 0..31 (group of 64 n)
    int nl = tid & 63;                 // 0..63
    int fc = tid >> 6;                 // 0..3  (f-chunk)
    int n  = ng * 64 + nl;

    const float* p = emb + ((size_t)(b * Ff + fc * 32)) * Nn + n;
    const float* pv = sv + fc * 32;

    float s = 0.f, sum = 0.f, sq = 0.f;
#pragma unroll
    for (int f = 0; f < 32; f++) {
        float x = __ldg(p + (size_t)f * Nn);
        s   = fmaf(pv[f], x, s);
        sum += x;
        sq  = fmaf(x, x, sq);
    }
    spart[tid] = s;
    __syncthreads();
    if (tid < 64) {
        float tot = spart[tid] + spart[64 + tid] + spart[128 + tid] + spart[192 + tid];
        g_s[b * Nn + ng * 64 + tid] = tot;
    }

    // block reduce sum & sq -> double atomics
    int lane = tid & 31;
    int wid  = tid >> 5;
#pragma unroll
    for (int o = 16; o > 0; o >>= 1) {
        sum += __shfl_xor_sync(0xffffffffu, sum, o);
        sq  += __shfl_xor_sync(0xffffffffu, sq, o);
    }
    if (lane == 0) { red_sum[wid] = sum; red_sq[wid] = sq; }
    __syncthreads();
    if (wid == 0) {
        float rs = (lane < 8) ? red_sum[lane] : 0.f;
        float rq = (lane < 8) ? red_sq[lane]  : 0.f;
#pragma unroll
        for (int o = 4; o > 0; o >>= 1) {
            rs += __shfl_xor_sync(0xffffffffu, rs, o);
            rq += __shfl_xor_sync(0xffffffffu, rq, o);
        }
        if (lane == 0) {
            atomicAdd(&g_sum, (double)rs);
            atomicAdd(&g_sumsq, (double)rq);
        }
    }
}

// ---------------------------------------------------------------------------
// Pass 2: E[n] = exp(-(s[n]*scale + bias/2)). scale computed per-block from
// the global accumulators (tid 0 -> smem broadcast).
// ---------------------------------------------------------------------------
__global__ void __launch_bounds__(512) k_exp(const float* __restrict__ bias) {
    __shared__ float sh_scale, sh_hb;
    if (threadIdx.x == 0) {
        double m   = (double)TOT;
        double var = (g_sumsq - g_sum * g_sum / m) / (m - 1.0);
        sh_scale = (float)(1.0 / sqrt(var));
        sh_hb    = 0.5f * bias[0];
    }
    __syncthreads();
    int idx = blockIdx.x * 512 + threadIdx.x;
    float t = fmaf(g_s[idx], sh_scale, sh_hb);
    g_E[idx] = __expf(-t);
}

// ---------------------------------------------------------------------------
// Pass 3: out[b,i,j] = 1 / (1 + E_i * E_j).
// Block = 512 threads handles 4 rows (same batch); each thread owns one
// float4 of j and writes it for all 4 rows -> E_j loaded once per 4 rows.
// Also re-zeroes the accumulators for the next graph replay (invariant:
// accumulators are zero at every kernel_launch entry; static init covers
// the first call).
// ---------------------------------------------------------------------------
__device__ __forceinline__ float frcp(float x) {
    float r;
    asm("rcp.approx.f32 %0, %1;" : "=f"(r) : "f"(x));
    return r;
}

__global__ void __launch_bounds__(512) k_main(float* __restrict__ out) {
    int r0 = blockIdx.x << 2;          // first of 4 rows, 0..32764
    int b  = r0 >> 11;

    const float4* Erow = (const float4*)(g_E + (size_t)b * Nn);
    float4 ej = __ldg(Erow + threadIdx.x);

    float p0 = __ldg(g_E + r0);
    float p1 = __ldg(g_E + r0 + 1);
    float p2 = __ldg(g_E + r0 + 2);
    float p3 = __ldg(g_E + r0 + 3);

    float4 o0, o1, o2, o3;
    o0.x = frcp(fmaf(p0, ej.x, 1.f)); o0.y = frcp(fmaf(p0, ej.y, 1.f));
    o0.z = frcp(fmaf(p0, ej.z, 1.f)); o0.w = frcp(fmaf(p0, ej.w, 1.f));
    o1.x = frcp(fmaf(p1, ej.x, 1.f)); o1.y = frcp(fmaf(p1, ej.y, 1.f));
    o1.z = frcp(fmaf(p1, ej.z, 1.f)); o1.w = frcp(fmaf(p1, ej.w, 1.f));
    o2.x = frcp(fmaf(p2, ej.x, 1.f)); o2.y = frcp(fmaf(p2, ej.y, 1.f));
    o2.z = frcp(fmaf(p2, ej.z, 1.f)); o2.w = frcp(fmaf(p2, ej.w, 1.f));
    o3.x = frcp(fmaf(p3, ej.x, 1.f)); o3.y = frcp(fmaf(p3, ej.y, 1.f));
    o3.z = frcp(fmaf(p3, ej.z, 1.f)); o3.w = frcp(fmaf(p3, ej.w, 1.f));

    float4* orow = (float4*)(out + (size_t)r0 * Nn) + threadIdx.x;
    orow[0]        = o0;
    orow[Nn / 4]   = o1;
    orow[Nn / 2]   = o2;
    orow[3 * Nn/4] = o3;

    if (blockIdx.x == 0 && threadIdx.x == 0) {
        g_sum = 0.0;
        g_sumsq = 0.0;
    }
}

extern "C" void kernel_launch(void* const* d_in, const int* in_sizes, int n_in,
                              void* d_out, int out_size) {
    // inputs: adj_in [B,N,N] (unused), emb_in [B,F,N], v [F], b [1]
    const float* emb  = (const float*)d_in[1];
    const float* v    = (const float*)d_in[2];
    const float* bias = (const float*)d_in[3];
    float* out = (float*)d_out;

    k_fused<<<512, 256>>>(emb, v);
    k_exp<<<BN / 512, 512>>>(bias);
    k_main<<<BN / 4, 512>>>(out);
}